// round 7
// baseline (speedup 1.0000x reference)
#include <cuda_runtime.h>
#include <cuda_bf16.h>
#include <cstdint>

// GraphSAGE on GB300 via mma.sync bf16 hi/lo (3-MMA fp32 emulation).
// R7: warp-specialized producer(4 warps gather/convert)/consumer(8 warps MMA)
// with named-barrier double buffering, so gather latency never blocks MMA issue.

#define N_NODES 100000
#define DIM     256
#define KDIM    512
#define NNEIGH  10
#define BM      64
#define KC      32
#define NCHUNK  16
#define THREADS 384
#define NCONS   256
#define NPROD   128

// smem (bytes)
#define ABUF    8192             // 64 rows x 128B (hi 64B | lo 64B)
#define WBASE   16384
#define WBUF    32768            // per W buffer: hi 16K + lo 16K
#define W_LO    16384
#define SMEM_TOTAL (WBASE + 2 * WBUF)   // 81920

// named barriers (0 is reserved for __syncthreads)
#define BAR_FULL0  1
#define BAR_FULL1  2
#define BAR_EMPTY0 3
#define BAR_EMPTY1 4

__device__ float g_buf0[(size_t)N_NODES * DIM];
__device__ float g_buf1[(size_t)N_NODES * DIM];
// W fragments in mma B-frag order: [layer][ktile(32)][ntile(32)][lane(32)][2] u32
__device__ uint32_t g_wfrag_hi[3][32 * 32 * 32 * 2];
__device__ uint32_t g_wfrag_lo[3][32 * 32 * 32 * 2];

__device__ __forceinline__ uint32_t smem_u32(const void* p) {
    uint32_t a;
    asm("{ .reg .u64 t; cvta.to.shared.u64 t, %1; cvt.u32.u64 %0, t; }" : "=r"(a) : "l"(p));
    return a;
}
__device__ __forceinline__ uint32_t sw128(uint32_t off) {
    return off ^ ((off >> 3) & 0x70);
}
__device__ __forceinline__ uint32_t pack_bf2(float a, float b) {
    __nv_bfloat162 t = __floats2bfloat162_rn(a, b);
    return *reinterpret_cast<uint32_t*>(&t);
}
__device__ __forceinline__ void ldmat4(uint32_t* r, uint32_t addr) {
    asm volatile("ldmatrix.sync.aligned.m8n8.x4.shared.b16 {%0,%1,%2,%3}, [%4];"
                 : "=r"(r[0]), "=r"(r[1]), "=r"(r[2]), "=r"(r[3]) : "r"(addr));
}
__device__ __forceinline__ void mma16816(float* c, const uint32_t* a, uint32_t b0, uint32_t b1) {
    asm volatile("mma.sync.aligned.m16n8k16.row.col.f32.bf16.bf16.f32 "
                 "{%0,%1,%2,%3}, {%4,%5,%6,%7}, {%8,%9}, {%0,%1,%2,%3};"
                 : "+f"(c[0]), "+f"(c[1]), "+f"(c[2]), "+f"(c[3])
                 : "r"(a[0]), "r"(a[1]), "r"(a[2]), "r"(a[3]), "r"(b0), "r"(b1));
}
__device__ __forceinline__ void cpasync16(uint32_t smem_dst, const void* gsrc) {
    asm volatile("cp.async.cg.shared.global [%0], [%1], 16;"
                 :: "r"(smem_dst), "l"(gsrc) : "memory");
}
__device__ __forceinline__ void cpasync_commit() {
    asm volatile("cp.async.commit_group;" ::: "memory");
}
__device__ __forceinline__ void cpasync_wait0() {
    asm volatile("cp.async.wait_group 0;" ::: "memory");
}
__device__ __forceinline__ void bar_sync(int id) {
    asm volatile("bar.sync %0, %1;" :: "r"(id), "r"(THREADS) : "memory");
}
__device__ __forceinline__ void bar_arrive(int id) {
    asm volatile("bar.arrive %0, %1;" :: "r"(id), "r"(THREADS) : "memory");
}
__device__ __forceinline__ void membar_cta() {
    asm volatile("membar.cta;" ::: "memory");
}

// -------- W prep: hi/lo split into mma B-fragment order (as R5) --------
__global__ void prep_wfrag(const float* __restrict__ W0, const float* __restrict__ W1,
                           const float* __restrict__ W2)
{
    int idx = blockIdx.x * blockDim.x + threadIdx.x;   // [layer][kt][nt][lane]
    if (idx >= 3 * 32 * 32 * 32) return;
    const int lane  = idx & 31;
    const int nt    = (idx >> 5) & 31;
    const int kt    = (idx >> 10) & 31;
    const int layer = idx >> 15;
    const float* W = layer == 0 ? W0 : (layer == 1 ? W1 : W2);
    const int k0 = kt * 16 + (lane & 3) * 2;
    const int n  = nt * 8 + (lane >> 2);

    float v[4] = { W[(k0 + 0) * DIM + n], W[(k0 + 1) * DIM + n],
                   W[(k0 + 8) * DIM + n], W[(k0 + 9) * DIM + n] };
    float hi[4], lo[4];
    #pragma unroll
    for (int i = 0; i < 4; ++i) {
        __nv_bfloat16 h = __float2bfloat16(v[i]);
        hi[i] = __bfloat162float(h);
        lo[i] = v[i] - hi[i];
    }
    const size_t base = ((size_t)(kt * 32 + nt) * 32 + lane) * 2;
    g_wfrag_hi[layer][base + 0] = pack_bf2(hi[0], hi[1]);
    g_wfrag_hi[layer][base + 1] = pack_bf2(hi[2], hi[3]);
    g_wfrag_lo[layer][base + 0] = pack_bf2(lo[0], lo[1]);
    g_wfrag_lo[layer][base + 1] = pack_bf2(lo[2], lo[3]);
}

// -------- fused SAGE layer: producer/consumer warp specialization --------
template <bool RELU>
__global__ __launch_bounds__(THREADS, 1)
void sage_mma(const float* __restrict__ hin, const int* __restrict__ adj,
              const uint32_t* __restrict__ wfh, const uint32_t* __restrict__ wfl,
              const float* __restrict__ bias, float* __restrict__ hout)
{
    extern __shared__ char smem[];
    const uint32_t sb = smem_u32(smem);
    const int tid  = threadIdx.x;
    const int lane = tid & 31;
    const int wid  = tid >> 5;
    const int row0 = blockIdx.x * BM;

    if (wid < 8) {
        // ================== CONSUMERS: 8 warps, 2m x 4n of 32x64 ==================
        const int wm = wid & 1;
        const int wn = wid >> 1;

        float c[2][8][4];
        #pragma unroll
        for (int i = 0; i < 2; ++i)
            #pragma unroll
            for (int j = 0; j < 8; ++j)
                #pragma unroll
                for (int k = 0; k < 4; ++k) c[i][j][k] = 0.f;

        for (int kc = 0; kc < NCHUNK; ++kc) {
            const int buf = kc & 1;
            bar_sync(BAR_FULL0 + buf);

            const uint32_t Ab = sb + buf * ABUF;
            const char*    Wp = smem + WBASE + buf * WBUF;
            #pragma unroll
            for (int kt = 0; kt < 2; ++kt) {
                uint32_t ah0[4], ah1[4], al0[4], al1[4];
                const uint32_t off0 = (uint32_t)((wm * 32 + (lane & 15)) * 128 + kt * 32 + (lane >> 4) * 16);
                const uint32_t off1 = off0 + 16 * 128;
                ldmat4(ah0, Ab + sw128(off0));
                ldmat4(ah1, Ab + sw128(off1));
                ldmat4(al0, Ab + sw128(off0 + 64));
                ldmat4(al1, Ab + sw128(off1 + 64));

                const uint2* bhp = (const uint2*)(Wp + ((size_t)(kt * 32 + wn * 8) * 32 + lane) * 8);
                const uint2* blp = (const uint2*)(Wp + W_LO + ((size_t)(kt * 32 + wn * 8) * 32 + lane) * 8);

                uint2 b[8];
                #pragma unroll
                for (int nt = 0; nt < 8; ++nt) b[nt] = bhp[nt * 32];
                #pragma unroll
                for (int nt = 0; nt < 8; ++nt) {         // hh
                    mma16816(c[0][nt], ah0, b[nt].x, b[nt].y);
                    mma16816(c[1][nt], ah1, b[nt].x, b[nt].y);
                }
                #pragma unroll
                for (int nt = 0; nt < 8; ++nt) {         // lh
                    mma16816(c[0][nt], al0, b[nt].x, b[nt].y);
                    mma16816(c[1][nt], al1, b[nt].x, b[nt].y);
                }
                #pragma unroll
                for (int nt = 0; nt < 8; ++nt) b[nt] = blp[nt * 32];
                #pragma unroll
                for (int nt = 0; nt < 8; ++nt) {         // hl
                    mma16816(c[0][nt], ah0, b[nt].x, b[nt].y);
                    mma16816(c[1][nt], ah1, b[nt].x, b[nt].y);
                }
            }
            bar_arrive(BAR_EMPTY0 + buf);
        }

        // ---------------- epilogue ----------------
        float2 bias2[8];
        #pragma unroll
        for (int nt = 0; nt < 8; ++nt)
            bias2[nt] = *(const float2*)&bias[wn * 64 + nt * 8 + (lane & 3) * 2];

        #pragma unroll
        for (int mt = 0; mt < 2; ++mt) {
            const int rbase = row0 + wm * 32 + mt * 16 + (lane >> 2);
            #pragma unroll
            for (int h = 0; h < 2; ++h) {
                const int row = rbase + h * 8;
                if (row < N_NODES) {
                    #pragma unroll
                    for (int nt = 0; nt < 8; ++nt) {
                        const int n = wn * 64 + nt * 8 + (lane & 3) * 2;
                        float2 o;
                        o.x = c[mt][nt][h * 2 + 0] + bias2[nt].x;
                        o.y = c[mt][nt][h * 2 + 1] + bias2[nt].y;
                        if (RELU) { o.x = fmaxf(o.x, 0.f); o.y = fmaxf(o.y, 0.f); }
                        *(float2*)(hout + (size_t)row * DIM + n) = o;
                    }
                }
            }
        }
    } else {
        // ================== PRODUCERS: 4 warps, 2 threads/row x 16 cols ==========
        const int ptid = tid - NCONS;        // 0..127
        const int pr   = ptid >> 1;          // row 0..63
        const int pq   = ptid & 1;           // 16-col half of the 32-col chunk
        const int prow = row0 + pr;
        const bool pvalid = prow < N_NODES;

        int adjreg[NNEIGH];
        #pragma unroll
        for (int j = 0; j < NNEIGH; ++j)
            adjreg[j] = pvalid ? adj[(size_t)prow * NNEIGH + j] : 0;

        for (int kc = 0; kc < NCHUNK; ++kc) {
            const int buf = kc & 1;
            if (kc >= 2) bar_sync(BAR_EMPTY0 + buf);

            // ---- W chunk slab via cp.async (32KB) ----
            {
                const uint32_t dst = sb + WBASE + buf * WBUF;
                const uint4* srcH = (const uint4*)(wfh + (size_t)kc * 4096);
                const uint4* srcL = (const uint4*)(wfl + (size_t)kc * 4096);
                #pragma unroll
                for (int i = 0; i < 8; ++i) {
                    const int e = ptid + i * NPROD;     // 1024 uint4 per half
                    cpasync16(dst + e * 16,        srcH + e);
                    cpasync16(dst + W_LO + e * 16, srcL + e);
                }
                cpasync_commit();
            }

            // ---- A gather: 16 cols ----
            float v[16];
            const int col = (kc & 7) * KC + pq * 16;
            if (pvalid) {
                if (kc < 8) {
                    const float4* s = (const float4*)(hin + (size_t)prow * DIM + col);
                    #pragma unroll
                    for (int g = 0; g < 4; ++g) {
                        float4 q = s[g];
                        v[g * 4 + 0] = q.x; v[g * 4 + 1] = q.y;
                        v[g * 4 + 2] = q.z; v[g * 4 + 3] = q.w;
                    }
                } else {
                    #pragma unroll
                    for (int i = 0; i < 16; ++i) v[i] = 0.f;
                    #pragma unroll
                    for (int j = 0; j < NNEIGH; ++j) {
                        const float4* s = (const float4*)(hin + (size_t)adjreg[j] * DIM + col);
                        #pragma unroll
                        for (int g = 0; g < 4; ++g) {
                            float4 q = s[g];
                            v[g * 4 + 0] += q.x; v[g * 4 + 1] += q.y;
                            v[g * 4 + 2] += q.z; v[g * 4 + 3] += q.w;
                        }
                    }
                    #pragma unroll
                    for (int i = 0; i < 16; ++i) v[i] *= (1.0f / NNEIGH);
                }
            } else {
                #pragma unroll
                for (int i = 0; i < 16; ++i) v[i] = 0.f;
            }

            // ---- hi/lo split + swizzled store ----
            uint32_t hv[8], lv[8];
            #pragma unroll
            for (int p = 0; p < 8; ++p) {
                const float f0 = v[2 * p], f1 = v[2 * p + 1];
                const __nv_bfloat16 h0 = __float2bfloat16(f0), h1 = __float2bfloat16(f1);
                hv[p] = pack_bf2(f0, f1);
                lv[p] = pack_bf2(f0 - __bfloat162float(h0), f1 - __bfloat162float(h1));
            }
            char* Ab = smem + buf * ABUF;
            const uint32_t off = (uint32_t)(pr * 128 + pq * 32);
            *(uint4*)(Ab + sw128(off))      = make_uint4(hv[0], hv[1], hv[2], hv[3]);
            *(uint4*)(Ab + sw128(off + 16)) = make_uint4(hv[4], hv[5], hv[6], hv[7]);
            *(uint4*)(Ab + sw128(off + 64)) = make_uint4(lv[0], lv[1], lv[2], lv[3]);
            *(uint4*)(Ab + sw128(off + 80)) = make_uint4(lv[4], lv[5], lv[6], lv[7]);

            cpasync_wait0();
            membar_cta();
            bar_arrive(BAR_FULL0 + buf);
        }
    }
}

extern "C" void kernel_launch(void* const* d_in, const int* in_sizes, int n_in,
                              void* d_out, int out_size)
{
    const float* x   = (const float*)d_in[0];
    const int*   adj = (const int*)  d_in[1];
    const float* W0  = (const float*)d_in[2];
    const float* b0  = (const float*)d_in[3];
    const float* W1  = (const float*)d_in[4];
    const float* b1  = (const float*)d_in[5];
    const float* W2  = (const float*)d_in[6];
    const float* b2  = (const float*)d_in[7];
    float* out = (float*)d_out;

    void *p0, *p1, *pwh, *pwl;
    cudaGetSymbolAddress(&p0, g_buf0);
    cudaGetSymbolAddress(&p1, g_buf1);
    cudaGetSymbolAddress(&pwh, g_wfrag_hi);
    cudaGetSymbolAddress(&pwl, g_wfrag_lo);
    float* h1 = (float*)p0;
    float* h2 = (float*)p1;
    const uint32_t* wh = (const uint32_t*)pwh;
    const uint32_t* wl = (const uint32_t*)pwl;
    const size_t WSZ = 32 * 32 * 32 * 2;

    cudaFuncSetAttribute(sage_mma<true>,
                         cudaFuncAttributeMaxDynamicSharedMemorySize, SMEM_TOTAL);
    cudaFuncSetAttribute(sage_mma<false>,
                         cudaFuncAttributeMaxDynamicSharedMemorySize, SMEM_TOTAL);

    prep_wfrag<<<(3 * 32 * 32 * 32 + 255) / 256, 256>>>(W0, W1, W2);

    const int grid = (N_NODES + BM - 1) / BM;   // 1563
    sage_mma<true ><<<grid, THREADS, SMEM_TOTAL>>>(x,  adj, wh,           wl,           b0, h1);
    sage_mma<true ><<<grid, THREADS, SMEM_TOTAL>>>(h1, adj, wh + WSZ,     wl + WSZ,     b1, h2);
    sage_mma<false><<<grid, THREADS, SMEM_TOTAL>>>(h2, adj, wh + 2 * WSZ, wl + 2 * WSZ, b2, out);
}

// round 8
// speedup vs baseline: 1.3400x; 1.3400x over previous
#include <cuda_runtime.h>
#include <cuda_bf16.h>
#include <cstdint>

// GraphSAGE on GB300 via mma.sync bf16 hi/lo (3-MMA fp32 emulation).
// R8: warp tile 32x32 (512 thr, BM=64 full-N). Each warp: issue gather LDGs for
// chunk kc+1 -> 48 MMAs on chunk kc -> consume. Gather latency hidden by the
// warp's own MMA block; no work duplication; no warp specialization.

#define N_NODES 100000
#define DIM     256
#define KDIM    512
#define NNEIGH  10
#define BM      64
#define KC      32
#define NCHUNK  16
#define THREADS 512

// smem (bytes)
#define ABUF    8192             // 64 rows x 128B (hi 64B | lo 64B)
#define WBASE   16384
#define WBUF    32768            // per W buffer: hi 16K + lo 16K
#define W_LO    16384
#define SMEM_TOTAL (WBASE + 2 * WBUF)   // 81920

__device__ float g_buf0[(size_t)N_NODES * DIM];
__device__ float g_buf1[(size_t)N_NODES * DIM];
// W fragments in mma B-frag order: [layer][ktile(32)][ntile(32)][lane(32)][2] u32
__device__ uint32_t g_wfrag_hi[3][32 * 32 * 32 * 2];
__device__ uint32_t g_wfrag_lo[3][32 * 32 * 32 * 2];

__device__ __forceinline__ uint32_t smem_u32(const void* p) {
    uint32_t a;
    asm("{ .reg .u64 t; cvta.to.shared.u64 t, %1; cvt.u32.u64 %0, t; }" : "=r"(a) : "l"(p));
    return a;
}
__device__ __forceinline__ uint32_t sw128(uint32_t off) {
    return off ^ ((off >> 3) & 0x70);
}
__device__ __forceinline__ uint32_t pack_bf2(float a, float b) {
    __nv_bfloat162 t = __floats2bfloat162_rn(a, b);
    return *reinterpret_cast<uint32_t*>(&t);
}
__device__ __forceinline__ void ldmat4(uint32_t* r, uint32_t addr) {
    asm volatile("ldmatrix.sync.aligned.m8n8.x4.shared.b16 {%0,%1,%2,%3}, [%4];"
                 : "=r"(r[0]), "=r"(r[1]), "=r"(r[2]), "=r"(r[3]) : "r"(addr));
}
__device__ __forceinline__ void mma16816(float* c, const uint32_t* a, uint32_t b0, uint32_t b1) {
    asm volatile("mma.sync.aligned.m16n8k16.row.col.f32.bf16.bf16.f32 "
                 "{%0,%1,%2,%3}, {%4,%5,%6,%7}, {%8,%9}, {%0,%1,%2,%3};"
                 : "+f"(c[0]), "+f"(c[1]), "+f"(c[2]), "+f"(c[3])
                 : "r"(a[0]), "r"(a[1]), "r"(a[2]), "r"(a[3]), "r"(b0), "r"(b1));
}
__device__ __forceinline__ void cpasync16(uint32_t smem_dst, const void* gsrc) {
    asm volatile("cp.async.cg.shared.global [%0], [%1], 16;"
                 :: "r"(smem_dst), "l"(gsrc) : "memory");
}
__device__ __forceinline__ void cpasync_commit() {
    asm volatile("cp.async.commit_group;" ::: "memory");
}
__device__ __forceinline__ void cpasync_wait0() {
    asm volatile("cp.async.wait_group 0;" ::: "memory");
}

// -------- W prep: hi/lo split into mma B-fragment order --------
__global__ void prep_wfrag(const float* __restrict__ W0, const float* __restrict__ W1,
                           const float* __restrict__ W2)
{
    int idx = blockIdx.x * blockDim.x + threadIdx.x;   // [layer][kt][nt][lane]
    if (idx >= 3 * 32 * 32 * 32) return;
    const int lane  = idx & 31;
    const int nt    = (idx >> 5) & 31;
    const int kt    = (idx >> 10) & 31;
    const int layer = idx >> 15;
    const float* W = layer == 0 ? W0 : (layer == 1 ? W1 : W2);
    const int k0 = kt * 16 + (lane & 3) * 2;
    const int n  = nt * 8 + (lane >> 2);

    float v[4] = { W[(k0 + 0) * DIM + n], W[(k0 + 1) * DIM + n],
                   W[(k0 + 8) * DIM + n], W[(k0 + 9) * DIM + n] };
    float hi[4], lo[4];
    #pragma unroll
    for (int i = 0; i < 4; ++i) {
        __nv_bfloat16 h = __float2bfloat16(v[i]);
        hi[i] = __bfloat162float(h);
        lo[i] = v[i] - hi[i];
    }
    const size_t base = ((size_t)(kt * 32 + nt) * 32 + lane) * 2;
    g_wfrag_hi[layer][base + 0] = pack_bf2(hi[0], hi[1]);
    g_wfrag_hi[layer][base + 1] = pack_bf2(hi[2], hi[3]);
    g_wfrag_lo[layer][base + 0] = pack_bf2(lo[0], lo[1]);
    g_wfrag_lo[layer][base + 1] = pack_bf2(lo[2], lo[3]);
}

// -------- fused SAGE layer --------
template <bool RELU>
__global__ __launch_bounds__(THREADS, 1)
void sage_mma(const float* __restrict__ hin, const int* __restrict__ adj,
              const uint32_t* __restrict__ wfh, const uint32_t* __restrict__ wfl,
              const float* __restrict__ bias, float* __restrict__ hout)
{
    extern __shared__ char smem[];
    const uint32_t sb = smem_u32(smem);
    const int tid  = threadIdx.x;
    const int lane = tid & 31;
    const int wid  = tid >> 5;
    const int wm   = wid & 1;     // rows wm*32..+31
    const int wn   = wid >> 1;    // cols wn*32..+31
    const int row0 = blockIdx.x * BM;

    // producer mapping: 8 threads/row, 4 cols each (fully coalesced gathers)
    const int pr = tid >> 3;         // row 0..63
    const int pq = tid & 7;          // 4-col slice of the 32-col chunk
    const int prow = row0 + pr;
    const bool pvalid = prow < N_NODES;

    float c[2][4][4];
    #pragma unroll
    for (int i = 0; i < 2; ++i)
        #pragma unroll
        for (int j = 0; j < 4; ++j)
            #pragma unroll
            for (int k = 0; k < 4; ++k) c[i][j][k] = 0.f;

    // ---- gather issue: LDGs into rw (held across the MMA block) ----
    auto issue = [&](int kc, float4* rw) {
        const int col = (kc & 7) * KC + pq * 4;
        if (!pvalid) return;
        if (kc < 8) {
            rw[0] = *(const float4*)(hin + (size_t)prow * DIM + col);
        } else {
            const int* arow = adj + (size_t)prow * NNEIGH;
            int na[NNEIGH];
            #pragma unroll
            for (int j = 0; j < NNEIGH; j += 2) {
                const int2 p = *(const int2*)(arow + j);
                na[j] = p.x; na[j + 1] = p.y;
            }
            #pragma unroll
            for (int j = 0; j < NNEIGH; ++j)
                rw[j] = *(const float4*)(hin + (size_t)na[j] * DIM + col);
        }
    };
    // ---- gather consume: mean, hi/lo split, swizzled A store ----
    auto consume = [&](int kc, const float4* rw) {
        float4 s = make_float4(0.f, 0.f, 0.f, 0.f);
        if (pvalid) {
            if (kc < 8) s = rw[0];
            else {
                #pragma unroll
                for (int j = 0; j < NNEIGH; ++j) {
                    s.x += rw[j].x; s.y += rw[j].y; s.z += rw[j].z; s.w += rw[j].w;
                }
                s.x *= 0.1f; s.y *= 0.1f; s.z *= 0.1f; s.w *= 0.1f;
            }
        }
        const __nv_bfloat16 hx = __float2bfloat16(s.x), hy = __float2bfloat16(s.y);
        const __nv_bfloat16 hz = __float2bfloat16(s.z), hw = __float2bfloat16(s.w);
        uint2 hv, lv;
        hv.x = pack_bf2(s.x, s.y);
        hv.y = pack_bf2(s.z, s.w);
        lv.x = pack_bf2(s.x - __bfloat162float(hx), s.y - __bfloat162float(hy));
        lv.y = pack_bf2(s.z - __bfloat162float(hz), s.w - __bfloat162float(hw));
        char* Ab = smem + (kc & 1) * ABUF;
        const uint32_t off = (uint32_t)(pr * 128 + pq * 8);
        *(uint2*)(Ab + sw128(off))      = hv;
        *(uint2*)(Ab + sw128(off + 64)) = lv;
    };
    // ---- W chunk slab via cp.async ----
    auto wcopy = [&](int kc) {
        const uint32_t dst = sb + WBASE + (kc & 1) * WBUF;
        const uint4* srcH = (const uint4*)(wfh + (size_t)kc * 4096);
        const uint4* srcL = (const uint4*)(wfl + (size_t)kc * 4096);
        #pragma unroll
        for (int i = 0; i < 2; ++i) {
            const int e = tid + i * THREADS;      // 1024 uint4 per half
            cpasync16(dst + e * 16,        srcH + e);
            cpasync16(dst + W_LO + e * 16, srcL + e);
        }
        cpasync_commit();
    };

    // ================= prologue =================
    wcopy(0);
    {
        float4 rw[NNEIGH];
        issue(0, rw);
        consume(0, rw);
    }
    cpasync_wait0();
    __syncthreads();

    // ================= main loop =================
    for (int kc = 0; kc < NCHUNK; ++kc) {
        const bool nxt = kc + 1 < NCHUNK;
        float4 rw[NNEIGH];
        if (nxt) {
            wcopy(kc + 1);
            issue(kc + 1, rw);   // LDGs in flight across the whole MMA block
        }

        // ---- MMA on chunk kc: 2 kt x 24 = 48 MMAs ----
        const uint32_t Ab = sb + (kc & 1) * ABUF;
        const char*    Wp = smem + WBASE + (kc & 1) * WBUF;
        #pragma unroll
        for (int kt = 0; kt < 2; ++kt) {
            uint32_t ah0[4], ah1[4], al0[4], al1[4];
            const uint32_t off0 = (uint32_t)((wm * 32 + (lane & 15)) * 128 + kt * 32 + (lane >> 4) * 16);
            const uint32_t off1 = off0 + 16 * 128;
            ldmat4(ah0, Ab + sw128(off0));
            ldmat4(ah1, Ab + sw128(off1));
            ldmat4(al0, Ab + sw128(off0 + 64));
            ldmat4(al1, Ab + sw128(off1 + 64));

            const uint2* bhp = (const uint2*)(Wp + ((size_t)(kt * 32 + wn * 4) * 32 + lane) * 8);
            const uint2* blp = (const uint2*)(Wp + W_LO + ((size_t)(kt * 32 + wn * 4) * 32 + lane) * 8);

            uint2 b[4];
            #pragma unroll
            for (int nt = 0; nt < 4; ++nt) b[nt] = bhp[nt * 32];
            #pragma unroll
            for (int nt = 0; nt < 4; ++nt) {          // hh: 8 independent
                mma16816(c[0][nt], ah0, b[nt].x, b[nt].y);
                mma16816(c[1][nt], ah1, b[nt].x, b[nt].y);
            }
            #pragma unroll
            for (int nt = 0; nt < 4; ++nt) {          // lh: 8 independent
                mma16816(c[0][nt], al0, b[nt].x, b[nt].y);
                mma16816(c[1][nt], al1, b[nt].x, b[nt].y);
            }
            #pragma unroll
            for (int nt = 0; nt < 4; ++nt) b[nt] = blp[nt * 32];
            #pragma unroll
            for (int nt = 0; nt < 4; ++nt) {          // hl: 8 independent
                mma16816(c[0][nt], ah0, b[nt].x, b[nt].y);
                mma16816(c[1][nt], ah1, b[nt].x, b[nt].y);
            }
        }

        if (nxt) {
            consume(kc + 1, rw);   // data arrived during the MMA block
            cpasync_wait0();
        }
        __syncthreads();
    }

    // ================= epilogue =================
    float2 bias2[4];
    #pragma unroll
    for (int nt = 0; nt < 4; ++nt)
        bias2[nt] = *(const float2*)&bias[wn * 32 + nt * 8 + (lane & 3) * 2];

    #pragma unroll
    for (int mt = 0; mt < 2; ++mt) {
        const int rbase = row0 + wm * 32 + mt * 16 + (lane >> 2);
        #pragma unroll
        for (int h = 0; h < 2; ++h) {
            const int row = rbase + h * 8;
            if (row < N_NODES) {
                #pragma unroll
                for (int nt = 0; nt < 4; ++nt) {
                    const int n = wn * 32 + nt * 8 + (lane & 3) * 2;
                    float2 o;
                    o.x = c[mt][nt][h * 2 + 0] + bias2[nt].x;
                    o.y = c[mt][nt][h * 2 + 1] + bias2[nt].y;
                    if (RELU) { o.x = fmaxf(o.x, 0.f); o.y = fmaxf(o.y, 0.f); }
                    *(float2*)(hout + (size_t)row * DIM + n) = o;
                }
            }
        }
    }
}

extern "C" void kernel_launch(void* const* d_in, const int* in_sizes, int n_in,
                              void* d_out, int out_size)
{
    const float* x   = (const float*)d_in[0];
    const int*   adj = (const int*)  d_in[1];
    const float* W0  = (const float*)d_in[2];
    const float* b0  = (const float*)d_in[3];
    const float* W1  = (const float*)d_in[4];
    const float* b1  = (const float*)d_in[5];
    const float* W2  = (const float*)d_in[6];
    const float* b2  = (const float*)d_in[7];
    float* out = (float*)d_out;

    void *p0, *p1, *pwh, *pwl;
    cudaGetSymbolAddress(&p0, g_buf0);
    cudaGetSymbolAddress(&p1, g_buf1);
    cudaGetSymbolAddress(&pwh, g_wfrag_hi);
    cudaGetSymbolAddress(&pwl, g_wfrag_lo);
    float* h1 = (float*)p0;
    float* h2 = (float*)p1;
    const uint32_t* wh = (const uint32_t*)pwh;
    const uint32_t* wl = (const uint32_t*)pwl;
    const size_t WSZ = 32 * 32 * 32 * 2;

    cudaFuncSetAttribute(sage_mma<true>,
                         cudaFuncAttributeMaxDynamicSharedMemorySize, SMEM_TOTAL);
    cudaFuncSetAttribute(sage_mma<false>,
                         cudaFuncAttributeMaxDynamicSharedMemorySize, SMEM_TOTAL);

    prep_wfrag<<<(3 * 32 * 32 * 32 + 255) / 256, 256>>>(W0, W1, W2);

    const int grid = (N_NODES + BM - 1) / BM;   // 1563
    sage_mma<true ><<<grid, THREADS, SMEM_TOTAL>>>(x,  adj, wh,           wl,           b0, h1);
    sage_mma<true ><<<grid, THREADS, SMEM_TOTAL>>>(h1, adj, wh + WSZ,     wl + WSZ,     b1, h2);
    sage_mma<false><<<grid, THREADS, SMEM_TOTAL>>>(h2, adj, wh + 2 * WSZ, wl + 2 * WSZ, b2, out);
}

// round 9
// speedup vs baseline: 1.4989x; 1.1186x over previous
#include <cuda_runtime.h>
#include <cuda_bf16.h>
#include <cstdint>

// GraphSAGE on GB300 via mma.sync bf16 hi/lo (3-MMA fp32 emulation).
// R9: R8's intra-warp issue->MMA->consume pipeline at BM=32 / 256 threads so
// TWO CTAs fit per SM (two independent barrier domains overlap each other's
// exposed phases). Warp tile 32x32 over full N=256.

#define N_NODES 100000
#define DIM     256
#define KDIM    512
#define NNEIGH  10
#define BM      32
#define KC      32
#define NCHUNK  16
#define THREADS 256

// smem (bytes)
#define ABUF    4096             // 32 rows x 128B (hi 64B | lo 64B)
#define WBASE   8192
#define WBUF    32768            // per W buffer: hi 16K + lo 16K
#define W_LO    16384
#define SMEM_TOTAL (WBASE + 2 * WBUF)   // 73728

__device__ float g_buf0[(size_t)N_NODES * DIM];
__device__ float g_buf1[(size_t)N_NODES * DIM];
// W fragments in mma B-frag order: [layer][ktile(32)][ntile(32)][lane(32)][2] u32
__device__ uint32_t g_wfrag_hi[3][32 * 32 * 32 * 2];
__device__ uint32_t g_wfrag_lo[3][32 * 32 * 32 * 2];

__device__ __forceinline__ uint32_t smem_u32(const void* p) {
    uint32_t a;
    asm("{ .reg .u64 t; cvta.to.shared.u64 t, %1; cvt.u32.u64 %0, t; }" : "=r"(a) : "l"(p));
    return a;
}
__device__ __forceinline__ uint32_t sw128(uint32_t off) {
    return off ^ ((off >> 3) & 0x70);
}
__device__ __forceinline__ uint32_t pack_bf2(float a, float b) {
    __nv_bfloat162 t = __floats2bfloat162_rn(a, b);
    return *reinterpret_cast<uint32_t*>(&t);
}
__device__ __forceinline__ void ldmat4(uint32_t* r, uint32_t addr) {
    asm volatile("ldmatrix.sync.aligned.m8n8.x4.shared.b16 {%0,%1,%2,%3}, [%4];"
                 : "=r"(r[0]), "=r"(r[1]), "=r"(r[2]), "=r"(r[3]) : "r"(addr));
}
__device__ __forceinline__ void mma16816(float* c, const uint32_t* a, uint32_t b0, uint32_t b1) {
    asm volatile("mma.sync.aligned.m16n8k16.row.col.f32.bf16.bf16.f32 "
                 "{%0,%1,%2,%3}, {%4,%5,%6,%7}, {%8,%9}, {%0,%1,%2,%3};"
                 : "+f"(c[0]), "+f"(c[1]), "+f"(c[2]), "+f"(c[3])
                 : "r"(a[0]), "r"(a[1]), "r"(a[2]), "r"(a[3]), "r"(b0), "r"(b1));
}
__device__ __forceinline__ void cpasync16(uint32_t smem_dst, const void* gsrc) {
    asm volatile("cp.async.cg.shared.global [%0], [%1], 16;"
                 :: "r"(smem_dst), "l"(gsrc) : "memory");
}
__device__ __forceinline__ void cpasync_commit() {
    asm volatile("cp.async.commit_group;" ::: "memory");
}
__device__ __forceinline__ void cpasync_wait0() {
    asm volatile("cp.async.wait_group 0;" ::: "memory");
}

// -------- W prep: hi/lo split into mma B-fragment order --------
__global__ void prep_wfrag(const float* __restrict__ W0, const float* __restrict__ W1,
                           const float* __restrict__ W2)
{
    int idx = blockIdx.x * blockDim.x + threadIdx.x;   // [layer][kt][nt][lane]
    if (idx >= 3 * 32 * 32 * 32) return;
    const int lane  = idx & 31;
    const int nt    = (idx >> 5) & 31;
    const int kt    = (idx >> 10) & 31;
    const int layer = idx >> 15;
    const float* W = layer == 0 ? W0 : (layer == 1 ? W1 : W2);
    const int k0 = kt * 16 + (lane & 3) * 2;
    const int n  = nt * 8 + (lane >> 2);

    float v[4] = { W[(k0 + 0) * DIM + n], W[(k0 + 1) * DIM + n],
                   W[(k0 + 8) * DIM + n], W[(k0 + 9) * DIM + n] };
    float hi[4], lo[4];
    #pragma unroll
    for (int i = 0; i < 4; ++i) {
        __nv_bfloat16 h = __float2bfloat16(v[i]);
        hi[i] = __bfloat162float(h);
        lo[i] = v[i] - hi[i];
    }
    const size_t base = ((size_t)(kt * 32 + nt) * 32 + lane) * 2;
    g_wfrag_hi[layer][base + 0] = pack_bf2(hi[0], hi[1]);
    g_wfrag_hi[layer][base + 1] = pack_bf2(hi[2], hi[3]);
    g_wfrag_lo[layer][base + 0] = pack_bf2(lo[0], lo[1]);
    g_wfrag_lo[layer][base + 1] = pack_bf2(lo[2], lo[3]);
}

// -------- fused SAGE layer --------
template <bool RELU>
__global__ __launch_bounds__(THREADS, 2)
void sage_mma(const float* __restrict__ hin, const int* __restrict__ adj,
              const uint32_t* __restrict__ wfh, const uint32_t* __restrict__ wfl,
              const float* __restrict__ bias, float* __restrict__ hout)
{
    extern __shared__ char smem[];
    const uint32_t sb = smem_u32(smem);
    const int tid  = threadIdx.x;
    const int lane = tid & 31;
    const int wn   = tid >> 5;       // warp n position (cols wn*32..+31)
    const int row0 = blockIdx.x * BM;

    // producer mapping: 8 threads/row, 4 cols each (fully coalesced gathers)
    const int pr = tid >> 3;         // row 0..31
    const int pq = tid & 7;          // 4-col slice of the 32-col chunk
    const int prow = row0 + pr;
    const bool pvalid = prow < N_NODES;   // always true (100000 % 32 == 0)

    float c[2][4][4];
    #pragma unroll
    for (int i = 0; i < 2; ++i)
        #pragma unroll
        for (int j = 0; j < 4; ++j)
            #pragma unroll
            for (int k = 0; k < 4; ++k) c[i][j][k] = 0.f;

    // ---- gather issue: LDGs into rw (held across the MMA block) ----
    auto issue = [&](int kc, float4* rw) {
        const int col = (kc & 7) * KC + pq * 4;
        if (!pvalid) return;
        if (kc < 8) {
            rw[0] = *(const float4*)(hin + (size_t)prow * DIM + col);
        } else {
            const int* arow = adj + (size_t)prow * NNEIGH;
            int na[NNEIGH];
            #pragma unroll
            for (int j = 0; j < NNEIGH; j += 2) {
                const int2 p = *(const int2*)(arow + j);
                na[j] = p.x; na[j + 1] = p.y;
            }
            #pragma unroll
            for (int j = 0; j < NNEIGH; ++j)
                rw[j] = *(const float4*)(hin + (size_t)na[j] * DIM + col);
        }
    };
    // ---- gather consume: mean, hi/lo split, swizzled A store ----
    auto consume = [&](int kc, const float4* rw) {
        float4 s = make_float4(0.f, 0.f, 0.f, 0.f);
        if (pvalid) {
            if (kc < 8) s = rw[0];
            else {
                #pragma unroll
                for (int j = 0; j < NNEIGH; ++j) {
                    s.x += rw[j].x; s.y += rw[j].y; s.z += rw[j].z; s.w += rw[j].w;
                }
                s.x *= 0.1f; s.y *= 0.1f; s.z *= 0.1f; s.w *= 0.1f;
            }
        }
        const __nv_bfloat16 hx = __float2bfloat16(s.x), hy = __float2bfloat16(s.y);
        const __nv_bfloat16 hz = __float2bfloat16(s.z), hw = __float2bfloat16(s.w);
        uint2 hv, lv;
        hv.x = pack_bf2(s.x, s.y);
        hv.y = pack_bf2(s.z, s.w);
        lv.x = pack_bf2(s.x - __bfloat162float(hx), s.y - __bfloat162float(hy));
        lv.y = pack_bf2(s.z - __bfloat162float(hz), s.w - __bfloat162float(hw));
        char* Ab = smem + (kc & 1) * ABUF;
        const uint32_t off = (uint32_t)(pr * 128 + pq * 8);
        *(uint2*)(Ab + sw128(off))      = hv;
        *(uint2*)(Ab + sw128(off + 64)) = lv;
    };
    // ---- W chunk slab via cp.async ----
    auto wcopy = [&](int kc) {
        const uint32_t dst = sb + WBASE + (kc & 1) * WBUF;
        const uint4* srcH = (const uint4*)(wfh + (size_t)kc * 4096);
        const uint4* srcL = (const uint4*)(wfl + (size_t)kc * 4096);
        #pragma unroll
        for (int i = 0; i < 4; ++i) {
            const int e = tid + i * THREADS;      // 1024 uint4 per half
            cpasync16(dst + e * 16,        srcH + e);
            cpasync16(dst + W_LO + e * 16, srcL + e);
        }
        cpasync_commit();
    };

    // ================= prologue =================
    wcopy(0);
    {
        float4 rw[NNEIGH];
        issue(0, rw);
        consume(0, rw);
    }
    cpasync_wait0();
    __syncthreads();

    // ================= main loop =================
    for (int kc = 0; kc < NCHUNK; ++kc) {
        const bool nxt = kc + 1 < NCHUNK;
        float4 rw[NNEIGH];
        if (nxt) {
            wcopy(kc + 1);
            issue(kc + 1, rw);   // LDGs in flight across the whole MMA block
        }

        // ---- MMA on chunk kc: 2 kt x 24 = 48 MMAs ----
        const uint32_t Ab = sb + (kc & 1) * ABUF;
        const char*    Wp = smem + WBASE + (kc & 1) * WBUF;
        #pragma unroll
        for (int kt = 0; kt < 2; ++kt) {
            uint32_t ah0[4], ah1[4], al0[4], al1[4];
            const uint32_t off0 = (uint32_t)((lane & 15) * 128 + kt * 32 + (lane >> 4) * 16);
            const uint32_t off1 = off0 + 16 * 128;
            ldmat4(ah0, Ab + sw128(off0));
            ldmat4(ah1, Ab + sw128(off1));
            ldmat4(al0, Ab + sw128(off0 + 64));
            ldmat4(al1, Ab + sw128(off1 + 64));

            const uint2* bhp = (const uint2*)(Wp + ((size_t)(kt * 32 + wn * 4) * 32 + lane) * 8);
            const uint2* blp = (const uint2*)(Wp + W_LO + ((size_t)(kt * 32 + wn * 4) * 32 + lane) * 8);

            uint2 b[4];
            #pragma unroll
            for (int nt = 0; nt < 4; ++nt) b[nt] = bhp[nt * 32];
            #pragma unroll
            for (int nt = 0; nt < 4; ++nt) {          // hh: 8 independent
                mma16816(c[0][nt], ah0, b[nt].x, b[nt].y);
                mma16816(c[1][nt], ah1, b[nt].x, b[nt].y);
            }
            #pragma unroll
            for (int nt = 0; nt < 4; ++nt) {          // lh: 8 independent
                mma16816(c[0][nt], al0, b[nt].x, b[nt].y);
                mma16816(c[1][nt], al1, b[nt].x, b[nt].y);
            }
            #pragma unroll
            for (int nt = 0; nt < 4; ++nt) b[nt] = blp[nt * 32];
            #pragma unroll
            for (int nt = 0; nt < 4; ++nt) {          // hl: 8 independent
                mma16816(c[0][nt], ah0, b[nt].x, b[nt].y);
                mma16816(c[1][nt], ah1, b[nt].x, b[nt].y);
            }
        }

        if (nxt) {
            consume(kc + 1, rw);   // data arrived during the MMA block
            cpasync_wait0();
        }
        __syncthreads();
    }

    // ================= epilogue =================
    // accumulator rows: ah0 covers rows (lane&15), ah1 covers rows +16
    float2 bias2[4];
    #pragma unroll
    for (int nt = 0; nt < 4; ++nt)
        bias2[nt] = *(const float2*)&bias[wn * 32 + nt * 8 + (lane & 3) * 2];

    #pragma unroll
    for (int mt = 0; mt < 2; ++mt) {
        const int rbase = row0 + mt * 16 + (lane >> 2);
        #pragma unroll
        for (int h = 0; h < 2; ++h) {
            const int row = rbase + h * 8;
            if (row < N_NODES) {
                #pragma unroll
                for (int nt = 0; nt < 4; ++nt) {
                    const int n = wn * 32 + nt * 8 + (lane & 3) * 2;
                    float2 o;
                    o.x = c[mt][nt][h * 2 + 0] + bias2[nt].x;
                    o.y = c[mt][nt][h * 2 + 1] + bias2[nt].y;
                    if (RELU) { o.x = fmaxf(o.x, 0.f); o.y = fmaxf(o.y, 0.f); }
                    *(float2*)(hout + (size_t)row * DIM + n) = o;
                }
            }
        }
    }
}

extern "C" void kernel_launch(void* const* d_in, const int* in_sizes, int n_in,
                              void* d_out, int out_size)
{
    const float* x   = (const float*)d_in[0];
    const int*   adj = (const int*)  d_in[1];
    const float* W0  = (const float*)d_in[2];
    const float* b0  = (const float*)d_in[3];
    const float* W1  = (const float*)d_in[4];
    const float* b1  = (const float*)d_in[5];
    const float* W2  = (const float*)d_in[6];
    const float* b2  = (const float*)d_in[7];
    float* out = (float*)d_out;

    void *p0, *p1, *pwh, *pwl;
    cudaGetSymbolAddress(&p0, g_buf0);
    cudaGetSymbolAddress(&p1, g_buf1);
    cudaGetSymbolAddress(&pwh, g_wfrag_hi);
    cudaGetSymbolAddress(&pwl, g_wfrag_lo);
    float* h1 = (float*)p0;
    float* h2 = (float*)p1;
    const uint32_t* wh = (const uint32_t*)pwh;
    const uint32_t* wl = (const uint32_t*)pwl;
    const size_t WSZ = 32 * 32 * 32 * 2;

    cudaFuncSetAttribute(sage_mma<true>,
                         cudaFuncAttributeMaxDynamicSharedMemorySize, SMEM_TOTAL);
    cudaFuncSetAttribute(sage_mma<false>,
                         cudaFuncAttributeMaxDynamicSharedMemorySize, SMEM_TOTAL);

    prep_wfrag<<<(3 * 32 * 32 * 32 + 255) / 256, 256>>>(W0, W1, W2);

    const int grid = (N_NODES + BM - 1) / BM;   // 3125
    sage_mma<true ><<<grid, THREADS, SMEM_TOTAL>>>(x,  adj, wh,           wl,           b0, h1);
    sage_mma<true ><<<grid, THREADS, SMEM_TOTAL>>>(h1, adj, wh + WSZ,     wl + WSZ,     b1, h2);
    sage_mma<false><<<grid, THREADS, SMEM_TOTAL>>>(h2, adj, wh + 2 * WSZ, wl + 2 * WSZ, b2, out);
}